// round 1
// baseline (speedup 1.0000x reference)
#include <cuda_runtime.h>
#include <math.h>
#include <stdint.h>

// Problem constants
#define B_ 4
#define T_ 4096
#define C_ 1024
#define H_ 128
#define M_ (B_ * T_)

// Scratch for projections (no cudaMalloc allowed)
__device__ float g_k[M_ * H_];
__device__ float g_q[M_ * H_];
__device__ float g_v[M_ * H_];

// ---------------------------------------------------------------------------
// Projection GEMM: y[M,H] = x[M,C] @ W[C,H]
// BM=128, BN=128(=H), BK=8, 256 threads, 8x8 micro-tile per thread.
// ---------------------------------------------------------------------------
__global__ __launch_bounds__(256) void proj_kernel(const float* __restrict__ x,
                                                   const float* __restrict__ W,
                                                   float* __restrict__ y) {
    __shared__ float As[8][132];  // As[kk][m], 132 keeps rows 16B-aligned + depads banks
    __shared__ float Bs[8][132];  // Bs[kk][n]

    const int m0  = blockIdx.x * 128;
    const int tid = threadIdx.x;
    const int tr  = tid >> 4;   // 0..15 -> row group
    const int tc  = tid & 15;   // 0..15 -> col group
    const int row0 = tr * 8;
    const int col0 = tc * 8;

    float acc[8][8];
#pragma unroll
    for (int i = 0; i < 8; i++)
#pragma unroll
        for (int j = 0; j < 8; j++) acc[i][j] = 0.0f;

    for (int k0 = 0; k0 < C_; k0 += 8) {
        // Load A slab: x[m0+m][k0..k0+8) -> As[kk][m]
        {
            int m  = tid >> 1;
            int kk = (tid & 1) * 4;
            float4 xv = *(const float4*)&x[(size_t)(m0 + m) * C_ + k0 + kk];
            As[kk + 0][m] = xv.x;
            As[kk + 1][m] = xv.y;
            As[kk + 2][m] = xv.z;
            As[kk + 3][m] = xv.w;
        }
        // Load B slab: W[k0+kk][n] -> Bs[kk][n]
        {
            int kk = tid >> 5;
            int n  = (tid & 31) * 4;
            float4 wv = *(const float4*)&W[(size_t)(k0 + kk) * H_ + n];
            *(float4*)&Bs[kk][n] = wv;
        }
        __syncthreads();

#pragma unroll
        for (int kk = 0; kk < 8; kk++) {
            const float4* A4 = (const float4*)&As[kk][0];
            const float4* B4 = (const float4*)&Bs[kk][0];
            float4 a0 = A4[tr * 2], a1 = A4[tr * 2 + 1];
            float4 b0 = B4[tc * 2], b1 = B4[tc * 2 + 1];
            float a[8] = {a0.x, a0.y, a0.z, a0.w, a1.x, a1.y, a1.z, a1.w};
            float b[8] = {b0.x, b0.y, b0.z, b0.w, b1.x, b1.y, b1.z, b1.w};
#pragma unroll
            for (int i = 0; i < 8; i++)
#pragma unroll
                for (int j = 0; j < 8; j++) acc[i][j] = fmaf(a[i], b[j], acc[i][j]);
        }
        __syncthreads();
    }

#pragma unroll
    for (int i = 0; i < 8; i++) {
#pragma unroll
        for (int j = 0; j < 8; j += 4) {
            float4 o = make_float4(acc[i][j], acc[i][j + 1], acc[i][j + 2], acc[i][j + 3]);
            *(float4*)&y[(size_t)(m0 + row0 + i) * H_ + col0 + j] = o;
        }
    }
}

// ---------------------------------------------------------------------------
// Flash attention (fp32), reference semantics:
//   s[i,j] = (k_i . q_j) / sqrt(C),  causal j<=i, softmax over j, out = P @ V
// BM=64 query(k)-rows per CTA, BN=64 key(q)-cols per tile, 256 threads / 8 warps.
// Warp w owns local rows [8w, 8w+8). Lane (r=lane>>3, c=lane&7):
//   S phase: rows {8w+r, 8w+r+4}, cols [8c, 8c+8)   -> 2x8 accumulators
//   O phase: rows {8w+r, 8w+r+4}, dims [16c, 16c+16)-> 2x16 accumulators
// ---------------------------------------------------------------------------
#define BM 64
#define BN 64
#define KQV_S (H_ + 4)   // 132 floats per row (16B-aligned)
#define PS_S  (BN + 4)   // 68
#define SMEM_FLOATS (3 * BM * KQV_S + BM * PS_S)
#define SMEM_BYTES  (SMEM_FLOATS * 4)

__global__ __launch_bounds__(256) void attn_kernel(float* __restrict__ out) {
    extern __shared__ float smem[];
    float* Ks = smem;
    float* Qs = Ks + BM * KQV_S;
    float* Vs = Qs + BM * KQV_S;
    float* Ps = Vs + BM * KQV_S;

    const int b       = blockIdx.y;
    const int n_tiles = T_ / BM;                   // 64
    const int i_tile  = n_tiles - 1 - blockIdx.x;  // heavy (long) tiles first
    const int i0      = i_tile * BM;

    const int tid  = threadIdx.x;
    const int warp = tid >> 5;
    const int lane = tid & 31;
    const int r    = lane >> 3;  // 0..3
    const int c    = lane & 7;   // 0..7
    const int row_a = warp * 8 + r;
    const int row_b = row_a + 4;

    // Load K tile (reused across all j-tiles)
    {
        const float4* s4 = (const float4*)(g_k + ((size_t)b * T_ + i0) * H_);
#pragma unroll
        for (int t = 0; t < 8; t++) {
            int idx = tid + t * 256;        // 0..2047 float4s (64 rows x 32)
            int row = idx >> 5;
            int d4  = idx & 31;
            *(float4*)&Ks[row * KQV_S + d4 * 4] = s4[idx];
        }
    }

    float o[2][16];
#pragma unroll
    for (int t = 0; t < 2; t++)
#pragma unroll
        for (int d = 0; d < 16; d++) o[t][d] = 0.0f;
    float m[2] = {-1e30f, -1e30f};
    float l[2] = {0.0f, 0.0f};

    const int nj = i_tile + 1;
    for (int jt = 0; jt < nj; jt++) {
        const int j0 = jt * BN;

        __syncthreads();  // previous iter done reading Qs/Vs/Ps (and K load done on iter 0)
        {
            const float4* qsrc = (const float4*)(g_q + ((size_t)b * T_ + j0) * H_);
            const float4* vsrc = (const float4*)(g_v + ((size_t)b * T_ + j0) * H_);
#pragma unroll
            for (int t = 0; t < 8; t++) {
                int idx = tid + t * 256;
                int row = idx >> 5;
                int d4  = idx & 31;
                *(float4*)&Qs[row * KQV_S + d4 * 4] = qsrc[idx];
                *(float4*)&Vs[row * KQV_S + d4 * 4] = vsrc[idx];
            }
        }
        __syncthreads();

        // ---- S = K_i . Q_j^T  (per-lane 2 rows x 8 cols) ----
        float s[2][8];
#pragma unroll
        for (int u = 0; u < 8; u++) { s[0][u] = 0.0f; s[1][u] = 0.0f; }

        const float* ka = &Ks[row_a * KQV_S];
        const float* kb = &Ks[row_b * KQV_S];
#pragma unroll 4
        for (int k4 = 0; k4 < H_ / 4; k4++) {
            float4 a0 = *(const float4*)&ka[k4 * 4];
            float4 a1 = *(const float4*)&kb[k4 * 4];
#pragma unroll
            for (int u = 0; u < 8; u++) {
                float4 qv = *(const float4*)&Qs[(8 * c + u) * KQV_S + k4 * 4];
                s[0][u] = fmaf(a0.x, qv.x, s[0][u]);
                s[0][u] = fmaf(a0.y, qv.y, s[0][u]);
                s[0][u] = fmaf(a0.z, qv.z, s[0][u]);
                s[0][u] = fmaf(a0.w, qv.w, s[0][u]);
                s[1][u] = fmaf(a1.x, qv.x, s[1][u]);
                s[1][u] = fmaf(a1.y, qv.y, s[1][u]);
                s[1][u] = fmaf(a1.z, qv.z, s[1][u]);
                s[1][u] = fmaf(a1.w, qv.w, s[1][u]);
            }
        }

        // ---- scale + causal mask (only the diagonal tile has masked entries) ----
        const bool diag = (jt == i_tile);
#pragma unroll
        for (int t = 0; t < 2; t++) {
            const int gi = i0 + (t ? row_b : row_a);
#pragma unroll
            for (int u = 0; u < 8; u++) {
                float val = s[t][u] * 0.03125f;  // C^-0.5 = 1/32
                if (diag && (j0 + 8 * c + u > gi)) val = -1e30f;
                s[t][u] = val;
            }
        }

        // ---- online softmax (row stats live across 8 lanes sharing r) ----
#pragma unroll
        for (int t = 0; t < 2; t++) {
            float tmax = s[t][0];
#pragma unroll
            for (int u = 1; u < 8; u++) tmax = fmaxf(tmax, s[t][u]);
            tmax = fmaxf(tmax, __shfl_xor_sync(0xffffffffu, tmax, 1));
            tmax = fmaxf(tmax, __shfl_xor_sync(0xffffffffu, tmax, 2));
            tmax = fmaxf(tmax, __shfl_xor_sync(0xffffffffu, tmax, 4));
            float m_new = fmaxf(m[t], tmax);
            float scale = __expf(m[t] - m_new);
            m[t] = m_new;
            float rsum = 0.0f;
#pragma unroll
            for (int u = 0; u < 8; u++) {
                s[t][u] = __expf(s[t][u] - m_new);
                rsum += s[t][u];
            }
            rsum += __shfl_xor_sync(0xffffffffu, rsum, 1);
            rsum += __shfl_xor_sync(0xffffffffu, rsum, 2);
            rsum += __shfl_xor_sync(0xffffffffu, rsum, 4);
            l[t] = l[t] * scale + rsum;
#pragma unroll
            for (int d = 0; d < 16; d++) o[t][d] *= scale;
        }

        // ---- stage P through SMEM (per-warp rows; warp-local producer/consumer) ----
        *(float4*)&Ps[row_a * PS_S + 8 * c]     = make_float4(s[0][0], s[0][1], s[0][2], s[0][3]);
        *(float4*)&Ps[row_a * PS_S + 8 * c + 4] = make_float4(s[0][4], s[0][5], s[0][6], s[0][7]);
        *(float4*)&Ps[row_b * PS_S + 8 * c]     = make_float4(s[1][0], s[1][1], s[1][2], s[1][3]);
        *(float4*)&Ps[row_b * PS_S + 8 * c + 4] = make_float4(s[1][4], s[1][5], s[1][6], s[1][7]);
        __syncwarp();

        // ---- O += P @ V  (per-lane 2 rows x 16 dims) ----
        const float* p0r = &Ps[row_a * PS_S];
        const float* p1r = &Ps[row_b * PS_S];
#pragma unroll 2
        for (int j = 0; j < BN; j += 4) {
            float4 p0 = *(const float4*)&p0r[j];
            float4 p1 = *(const float4*)&p1r[j];
            float pa[4] = {p0.x, p0.y, p0.z, p0.w};
            float pb[4] = {p1.x, p1.y, p1.z, p1.w};
#pragma unroll
            for (int jj = 0; jj < 4; jj++) {
                const float* vr = &Vs[(j + jj) * KQV_S + c * 16];
#pragma unroll
                for (int d4 = 0; d4 < 4; d4++) {
                    float4 vv = *(const float4*)&vr[d4 * 4];
                    o[0][d4 * 4 + 0] = fmaf(pa[jj], vv.x, o[0][d4 * 4 + 0]);
                    o[0][d4 * 4 + 1] = fmaf(pa[jj], vv.y, o[0][d4 * 4 + 1]);
                    o[0][d4 * 4 + 2] = fmaf(pa[jj], vv.z, o[0][d4 * 4 + 2]);
                    o[0][d4 * 4 + 3] = fmaf(pa[jj], vv.w, o[0][d4 * 4 + 3]);
                    o[1][d4 * 4 + 0] = fmaf(pb[jj], vv.x, o[1][d4 * 4 + 0]);
                    o[1][d4 * 4 + 1] = fmaf(pb[jj], vv.y, o[1][d4 * 4 + 1]);
                    o[1][d4 * 4 + 2] = fmaf(pb[jj], vv.z, o[1][d4 * 4 + 2]);
                    o[1][d4 * 4 + 3] = fmaf(pb[jj], vv.w, o[1][d4 * 4 + 3]);
                }
            }
        }
    }

    // ---- epilogue: out = O / l ----
#pragma unroll
    for (int t = 0; t < 2; t++) {
        const int grow = i0 + (t ? row_b : row_a);
        const float inv = 1.0f / l[t];
        float* dst = out + ((size_t)b * T_ + grow) * H_ + c * 16;
#pragma unroll
        for (int d4 = 0; d4 < 4; d4++) {
            float4 ov = make_float4(o[t][d4 * 4 + 0] * inv, o[t][d4 * 4 + 1] * inv,
                                    o[t][d4 * 4 + 2] * inv, o[t][d4 * 4 + 3] * inv);
            *(float4*)&dst[d4 * 4] = ov;
        }
    }
}

// ---------------------------------------------------------------------------
extern "C" void kernel_launch(void* const* d_in, const int* in_sizes, int n_in,
                              void* d_out, int out_size) {
    const float* x  = (const float*)d_in[0];
    const float* Wk = (const float*)d_in[1];
    const float* Wq = (const float*)d_in[2];
    const float* Wv = (const float*)d_in[3];
    float* out = (float*)d_out;

    float *kp, *qp, *vp;
    cudaGetSymbolAddress((void**)&kp, g_k);
    cudaGetSymbolAddress((void**)&qp, g_q);
    cudaGetSymbolAddress((void**)&vp, g_v);

    cudaFuncSetAttribute(attn_kernel, cudaFuncAttributeMaxDynamicSharedMemorySize, SMEM_BYTES);

    dim3 pgrid(M_ / 128);
    proj_kernel<<<pgrid, 256>>>(x, Wk, kp);
    proj_kernel<<<pgrid, 256>>>(x, Wq, qp);
    proj_kernel<<<pgrid, 256>>>(x, Wv, vp);

    attn_kernel<<<dim3(T_ / BM, B_), 256, SMEM_BYTES>>>(out);
}

// round 2
// speedup vs baseline: 9.8544x; 9.8544x over previous
#include <cuda_runtime.h>
#include <math.h>
#include <stdint.h>

#define B_ 4
#define T_ 4096
#define C_ 1024
#define H_ 128
#define M_ (B_ * T_)

// tf32-rounded projection outputs (scratch; no cudaMalloc allowed)
__device__ float g_k[M_ * H_];
__device__ float g_q[M_ * H_];
__device__ float g_v[M_ * H_];

__device__ __forceinline__ unsigned f2tf(float x) {
    unsigned r;
    asm("cvt.rna.tf32.f32 %0, %1;" : "=r"(r) : "f"(x));
    return r;
}

__device__ __forceinline__ void mma8(float* c, unsigned a0, unsigned a1, unsigned a2, unsigned a3,
                                     unsigned b0, unsigned b1) {
    asm volatile(
        "mma.sync.aligned.m16n8k8.row.col.f32.tf32.tf32.f32 "
        "{%0,%1,%2,%3},{%4,%5,%6,%7},{%8,%9},{%0,%1,%2,%3};"
        : "+f"(c[0]), "+f"(c[1]), "+f"(c[2]), "+f"(c[3])
        : "r"(a0), "r"(a1), "r"(a2), "r"(a3), "r"(b0), "r"(b1));
}

// ---------------------------------------------------------------------------
// Projection: y[M,H] = tf32_round(x) @ tf32_round(W), output tf32-rounded.
// BM=128, BK=32, N=128. 8 warps as 4m x 2n; warp tile 32 rows x 64 cols.
// Strides: Xs 36 (mod32=4 -> conflict-free A frags), Ws 136 (mod32=8 -> B frags).
// ---------------------------------------------------------------------------
#define XS_S 36
#define WS_S 136

__global__ __launch_bounds__(256) void proj_kernel(const float* __restrict__ x,
                                                   const float* __restrict__ W,
                                                   float* __restrict__ y) {
    __shared__ float Xs[128 * XS_S];
    __shared__ float Ws[32 * WS_S];

    const int tid  = threadIdx.x;
    const int warp = tid >> 5;
    const int lane = tid & 31;
    const int g    = lane >> 2;  // groupID
    const int q    = lane & 3;   // threadID_in_group
    const int wm   = warp >> 1;  // 0..3
    const int wn   = warp & 1;   // 0..1
    const int m0   = blockIdx.x * 128;

    float acc[2][8][4];
#pragma unroll
    for (int mf = 0; mf < 2; mf++)
#pragma unroll
        for (int nb = 0; nb < 8; nb++)
#pragma unroll
            for (int k = 0; k < 4; k++) acc[mf][nb][k] = 0.0f;

    const unsigned* XsU = (const unsigned*)Xs;
    const unsigned* WsU = (const unsigned*)Ws;

    for (int k0 = 0; k0 < C_; k0 += 32) {
        __syncthreads();
        // Fill Xs[128][32] (rounded): 1024 float4
#pragma unroll
        for (int t = 0; t < 4; t++) {
            int idx = tid + t * 256;
            int row = idx >> 3, c4 = idx & 7;
            float4 v = *(const float4*)&x[(size_t)(m0 + row) * C_ + k0 + c4 * 4];
            float4 r = make_float4(__uint_as_float(f2tf(v.x)), __uint_as_float(f2tf(v.y)),
                                   __uint_as_float(f2tf(v.z)), __uint_as_float(f2tf(v.w)));
            *(float4*)&Xs[row * XS_S + c4 * 4] = r;
        }
        // Fill Ws[32][128] (rounded): 1024 float4
#pragma unroll
        for (int t = 0; t < 4; t++) {
            int idx = tid + t * 256;
            int row = idx >> 5, c4 = idx & 31;
            float4 v = *(const float4*)&W[(size_t)(k0 + row) * H_ + c4 * 4];
            float4 r = make_float4(__uint_as_float(f2tf(v.x)), __uint_as_float(f2tf(v.y)),
                                   __uint_as_float(f2tf(v.z)), __uint_as_float(f2tf(v.w)));
            *(float4*)&Ws[row * WS_S + c4 * 4] = r;
        }
        __syncthreads();

#pragma unroll
        for (int kc = 0; kc < 4; kc++) {
            unsigned a[2][4];
#pragma unroll
            for (int mf = 0; mf < 2; mf++) {
                int row = wm * 32 + mf * 16 + g;
                a[mf][0] = XsU[row * XS_S + kc * 8 + q];
                a[mf][1] = XsU[(row + 8) * XS_S + kc * 8 + q];
                a[mf][2] = XsU[row * XS_S + kc * 8 + q + 4];
                a[mf][3] = XsU[(row + 8) * XS_S + kc * 8 + q + 4];
            }
#pragma unroll
            for (int nb = 0; nb < 8; nb++) {
                int ncol = wn * 64 + nb * 8 + g;
                unsigned b0 = WsU[(kc * 8 + q) * WS_S + ncol];
                unsigned b1 = WsU[(kc * 8 + q + 4) * WS_S + ncol];
                mma8(acc[0][nb], a[0][0], a[0][1], a[0][2], a[0][3], b0, b1);
                mma8(acc[1][nb], a[1][0], a[1][1], a[1][2], a[1][3], b0, b1);
            }
        }
    }

    // Epilogue: store tf32-rounded (consumed as tf32 by attention)
#pragma unroll
    for (int mf = 0; mf < 2; mf++) {
        int row = m0 + wm * 32 + mf * 16 + g;
#pragma unroll
        for (int nb = 0; nb < 8; nb++) {
            int col = wn * 64 + nb * 8 + 2 * q;
            *(float2*)&y[(size_t)row * H_ + col] =
                make_float2(__uint_as_float(f2tf(acc[mf][nb][0])), __uint_as_float(f2tf(acc[mf][nb][1])));
            *(float2*)&y[(size_t)(row + 8) * H_ + col] =
                make_float2(__uint_as_float(f2tf(acc[mf][nb][2])), __uint_as_float(f2tf(acc[mf][nb][3])));
        }
    }
}

// ---------------------------------------------------------------------------
// Flash attention, tf32 mma. s[i,j] = (k_i . q_j)/32, causal, softmax, @V.
// BM=BN=64, 128 threads / 4 warps, warp w owns rows 16w..16w+15.
// Static balanced schedule: 148 CTAs; CTA c runs unit c (heavy) and 255-c (light).
// Unit idx (descending cost): i_tile = 63 - idx/4, b = idx&3.
// Strides: Ks/Qs 132, Vs 136, Ps 68 -> conflict-free fragment LDS.
// ---------------------------------------------------------------------------
#define AGRID 148
#define KQ_S 132
#define V_S  136
#define P_S  68
#define ASMEM_FLOATS (64 * KQ_S * 2 + 64 * V_S + 64 * P_S)
#define ASMEM_BYTES  (ASMEM_FLOATS * 4)

__global__ __launch_bounds__(128) void attn_kernel(float* __restrict__ out) {
    extern __shared__ float sm[];
    float* Ks = sm;
    float* Qs = Ks + 64 * KQ_S;
    float* Vs = Qs + 64 * KQ_S;
    float* Ps = Vs + 64 * V_S;
    const unsigned* KsU = (const unsigned*)Ks;
    const unsigned* QsU = (const unsigned*)Qs;
    const unsigned* VsU = (const unsigned*)Vs;
    const unsigned* PsU = (const unsigned*)Ps;

    const int c    = blockIdx.x;
    const int tid  = threadIdx.x;
    const int warp = tid >> 5;
    const int lane = tid & 31;
    const int g    = lane >> 2;
    const int q    = lane & 3;

    for (int u = 0; u < 2; u++) {
        if (u == 1 && c >= 256 - AGRID) break;
        const int idx    = (u == 0) ? c : 255 - c;
        const int i_tile = 63 - (idx >> 2);
        const int b      = idx & 3;
        const int i0     = i_tile * 64;

        __syncthreads();  // prior unit done with smem
        {
            const float4* ksrc = (const float4*)(g_k + ((size_t)b * T_ + i0) * H_);
#pragma unroll
            for (int t = 0; t < 16; t++) {
                int id = tid + t * 128;
                int row = id >> 5, c4 = id & 31;
                *(float4*)&Ks[row * KQ_S + c4 * 4] = ksrc[id];
            }
        }

        float o[16][4];
#pragma unroll
        for (int hb = 0; hb < 16; hb++)
#pragma unroll
            for (int k = 0; k < 4; k++) o[hb][k] = 0.0f;
        float mrow[2] = {-1e30f, -1e30f};
        float lrow[2] = {0.0f, 0.0f};

        const int rA = warp * 16 + g;   // local row (and +8)
        const int nj = i_tile + 1;

        for (int jt = 0; jt < nj; jt++) {
            const int j0 = jt * 64;
            __syncthreads();
            {
                const float4* qsrc = (const float4*)(g_q + ((size_t)b * T_ + j0) * H_);
                const float4* vsrc = (const float4*)(g_v + ((size_t)b * T_ + j0) * H_);
#pragma unroll
                for (int t = 0; t < 16; t++) {
                    int id = tid + t * 128;
                    int row = id >> 5, c4 = id & 31;
                    *(float4*)&Qs[row * KQ_S + c4 * 4] = qsrc[id];
                    *(float4*)&Vs[row * V_S + c4 * 4] = vsrc[id];
                }
            }
            __syncthreads();

            // ---- S = K @ Q^T ----
            float s[8][4];
#pragma unroll
            for (int nb = 0; nb < 8; nb++)
#pragma unroll
                for (int k = 0; k < 4; k++) s[nb][k] = 0.0f;

#pragma unroll
            for (int kc = 0; kc < 16; kc++) {
                unsigned a0 = KsU[rA * KQ_S + kc * 8 + q];
                unsigned a1 = KsU[(rA + 8) * KQ_S + kc * 8 + q];
                unsigned a2 = KsU[rA * KQ_S + kc * 8 + q + 4];
                unsigned a3 = KsU[(rA + 8) * KQ_S + kc * 8 + q + 4];
#pragma unroll
                for (int nb = 0; nb < 8; nb++) {
                    unsigned b0 = QsU[(nb * 8 + g) * KQ_S + kc * 8 + q];
                    unsigned b1 = QsU[(nb * 8 + g) * KQ_S + kc * 8 + q + 4];
                    mma8(s[nb], a0, a1, a2, a3, b0, b1);
                }
            }

            // ---- scale + causal mask ----
            const bool diag = (jt == i_tile);
#pragma unroll
            for (int nb = 0; nb < 8; nb++) {
                int jc = j0 + nb * 8 + 2 * q;
                int riA = i0 + rA, riB = riA + 8;
                float v0 = s[nb][0] * 0.03125f, v1 = s[nb][1] * 0.03125f;
                float v2 = s[nb][2] * 0.03125f, v3 = s[nb][3] * 0.03125f;
                if (diag) {
                    if (jc > riA) v0 = -1e30f;
                    if (jc + 1 > riA) v1 = -1e30f;
                    if (jc > riB) v2 = -1e30f;
                    if (jc + 1 > riB) v3 = -1e30f;
                }
                s[nb][0] = v0; s[nb][1] = v1; s[nb][2] = v2; s[nb][3] = v3;
            }

            // ---- online softmax (row stats across quad: lanes xor 1,2) ----
#pragma unroll
            for (int t = 0; t < 2; t++) {
                float tm = -1e30f;
#pragma unroll
                for (int nb = 0; nb < 8; nb++)
                    tm = fmaxf(tm, fmaxf(s[nb][2 * t], s[nb][2 * t + 1]));
                tm = fmaxf(tm, __shfl_xor_sync(0xffffffffu, tm, 1));
                tm = fmaxf(tm, __shfl_xor_sync(0xffffffffu, tm, 2));
                float mn = fmaxf(mrow[t], tm);
                float sc = __expf(mrow[t] - mn);
                mrow[t] = mn;
                float rs = 0.0f;
#pragma unroll
                for (int nb = 0; nb < 8; nb++) {
                    float p0 = __expf(s[nb][2 * t] - mn);
                    float p1 = __expf(s[nb][2 * t + 1] - mn);
                    s[nb][2 * t] = p0; s[nb][2 * t + 1] = p1;
                    rs += p0 + p1;
                }
                rs += __shfl_xor_sync(0xffffffffu, rs, 1);
                rs += __shfl_xor_sync(0xffffffffu, rs, 2);
                lrow[t] = lrow[t] * sc + rs;
#pragma unroll
                for (int hb = 0; hb < 16; hb++) {
                    o[hb][2 * t] *= sc; o[hb][2 * t + 1] *= sc;
                }
            }

            // ---- stage P (tf32-rounded) in warp-private Ps rows ----
#pragma unroll
            for (int nb = 0; nb < 8; nb++) {
                *(float2*)&Ps[rA * P_S + nb * 8 + 2 * q] =
                    make_float2(__uint_as_float(f2tf(s[nb][0])), __uint_as_float(f2tf(s[nb][1])));
                *(float2*)&Ps[(rA + 8) * P_S + nb * 8 + 2 * q] =
                    make_float2(__uint_as_float(f2tf(s[nb][2])), __uint_as_float(f2tf(s[nb][3])));
            }
            __syncwarp();

            // ---- O += P @ V ----
#pragma unroll
            for (int t8 = 0; t8 < 8; t8++) {
                unsigned a0 = PsU[rA * P_S + t8 * 8 + q];
                unsigned a1 = PsU[(rA + 8) * P_S + t8 * 8 + q];
                unsigned a2 = PsU[rA * P_S + t8 * 8 + q + 4];
                unsigned a3 = PsU[(rA + 8) * P_S + t8 * 8 + q + 4];
#pragma unroll
                for (int hb = 0; hb < 16; hb++) {
                    unsigned b0 = VsU[(t8 * 8 + q) * V_S + hb * 8 + g];
                    unsigned b1 = VsU[(t8 * 8 + q + 4) * V_S + hb * 8 + g];
                    mma8(o[hb], a0, a1, a2, a3, b0, b1);
                }
            }
        }

        // ---- epilogue: out = O / l (full fp32) ----
#pragma unroll
        for (int t = 0; t < 2; t++) {
            float inv = 1.0f / lrow[t];
            size_t rbase = ((size_t)b * T_ + i0 + rA + t * 8) * H_;
#pragma unroll
            for (int hb = 0; hb < 16; hb++) {
                *(float2*)&out[rbase + hb * 8 + 2 * q] =
                    make_float2(o[hb][2 * t] * inv, o[hb][2 * t + 1] * inv);
            }
        }
    }
}

// ---------------------------------------------------------------------------
extern "C" void kernel_launch(void* const* d_in, const int* in_sizes, int n_in,
                              void* d_out, int out_size) {
    const float* x  = (const float*)d_in[0];
    const float* Wk = (const float*)d_in[1];
    const float* Wq = (const float*)d_in[2];
    const float* Wv = (const float*)d_in[3];
    float* out = (float*)d_out;

    float *kp, *qp, *vp;
    cudaGetSymbolAddress((void**)&kp, g_k);
    cudaGetSymbolAddress((void**)&qp, g_q);
    cudaGetSymbolAddress((void**)&vp, g_v);

    cudaFuncSetAttribute(attn_kernel, cudaFuncAttributeMaxDynamicSharedMemorySize, ASMEM_BYTES);

    dim3 pgrid(M_ / 128);
    proj_kernel<<<pgrid, 256>>>(x, Wk, kp);
    proj_kernel<<<pgrid, 256>>>(x, Wq, qp);
    proj_kernel<<<pgrid, 256>>>(x, Wv, vp);

    attn_kernel<<<AGRID, 128, ASMEM_BYTES>>>(out);
}

// round 3
// speedup vs baseline: 15.9479x; 1.6184x over previous
#include <cuda_runtime.h>
#include <math.h>
#include <stdint.h>

#define B_ 4
#define T_ 4096
#define C_ 1024
#define H_ 128
#define M_ (B_ * T_)

// tf32-rounded projection outputs (scratch; no cudaMalloc allowed)
__device__ float g_k[M_ * H_];
__device__ float g_q[M_ * H_];
__device__ float g_v[M_ * H_];

__device__ __forceinline__ unsigned f2tf(float x) {
    unsigned r;
    asm("cvt.rna.tf32.f32 %0, %1;" : "=r"(r) : "f"(x));
    return r;
}

__device__ __forceinline__ void mma8(float* c, unsigned a0, unsigned a1, unsigned a2, unsigned a3,
                                     unsigned b0, unsigned b1) {
    asm volatile(
        "mma.sync.aligned.m16n8k8.row.col.f32.tf32.tf32.f32 "
        "{%0,%1,%2,%3},{%4,%5,%6,%7},{%8,%9},{%0,%1,%2,%3};"
        : "+f"(c[0]), "+f"(c[1]), "+f"(c[2]), "+f"(c[3])
        : "r"(a0), "r"(a1), "r"(a2), "r"(a3), "r"(b0), "r"(b1));
}

__device__ __forceinline__ void barg(int id) {
    asm volatile("bar.sync %0, 128;" ::"r"(id) : "memory");
}

// ---------------------------------------------------------------------------
// Fused projections: y_{k,q,v}[M,H] = tf32(x) @ tf32(W_*), grid (M/128, 3).
// ---------------------------------------------------------------------------
#define XS_S 36
#define WS_S 136

__global__ __launch_bounds__(256) void proj_kernel(const float* __restrict__ x,
                                                   const float* __restrict__ Wk,
                                                   const float* __restrict__ Wq,
                                                   const float* __restrict__ Wv) {
    __shared__ float Xs[128 * XS_S];
    __shared__ float Ws[32 * WS_S];

    const float* W = (blockIdx.y == 0) ? Wk : (blockIdx.y == 1) ? Wq : Wv;
    float* y = (blockIdx.y == 0) ? g_k : (blockIdx.y == 1) ? g_q : g_v;

    const int tid  = threadIdx.x;
    const int warp = tid >> 5;
    const int lane = tid & 31;
    const int g    = lane >> 2;
    const int q    = lane & 3;
    const int wm   = warp >> 1;
    const int wn   = warp & 1;
    const int m0   = blockIdx.x * 128;

    float acc[2][8][4];
#pragma unroll
    for (int mf = 0; mf < 2; mf++)
#pragma unroll
        for (int nb = 0; nb < 8; nb++)
#pragma unroll
            for (int k = 0; k < 4; k++) acc[mf][nb][k] = 0.0f;

    const unsigned* XsU = (const unsigned*)Xs;
    const unsigned* WsU = (const unsigned*)Ws;

    for (int k0 = 0; k0 < C_; k0 += 32) {
        __syncthreads();
#pragma unroll
        for (int t = 0; t < 4; t++) {
            int idx = tid + t * 256;
            int row = idx >> 3, c4 = idx & 7;
            float4 v = *(const float4*)&x[(size_t)(m0 + row) * C_ + k0 + c4 * 4];
            float4 r = make_float4(__uint_as_float(f2tf(v.x)), __uint_as_float(f2tf(v.y)),
                                   __uint_as_float(f2tf(v.z)), __uint_as_float(f2tf(v.w)));
            *(float4*)&Xs[row * XS_S + c4 * 4] = r;
        }
#pragma unroll
        for (int t = 0; t < 4; t++) {
            int idx = tid + t * 256;
            int row = idx >> 5, c4 = idx & 31;
            float4 v = *(const float4*)&W[(size_t)(k0 + row) * H_ + c4 * 4];
            float4 r = make_float4(__uint_as_float(f2tf(v.x)), __uint_as_float(f2tf(v.y)),
                                   __uint_as_float(f2tf(v.z)), __uint_as_float(f2tf(v.w)));
            *(float4*)&Ws[row * WS_S + c4 * 4] = r;
        }
        __syncthreads();

#pragma unroll
        for (int kc = 0; kc < 4; kc++) {
            unsigned a[2][4];
#pragma unroll
            for (int mf = 0; mf < 2; mf++) {
                int row = wm * 32 + mf * 16 + g;
                a[mf][0] = XsU[row * XS_S + kc * 8 + q];
                a[mf][1] = XsU[(row + 8) * XS_S + kc * 8 + q];
                a[mf][2] = XsU[row * XS_S + kc * 8 + q + 4];
                a[mf][3] = XsU[(row + 8) * XS_S + kc * 8 + q + 4];
            }
#pragma unroll
            for (int nb = 0; nb < 8; nb++) {
                int ncol = wn * 64 + nb * 8 + g;
                unsigned b0 = WsU[(kc * 8 + q) * WS_S + ncol];
                unsigned b1 = WsU[(kc * 8 + q + 4) * WS_S + ncol];
                mma8(acc[0][nb], a[0][0], a[0][1], a[0][2], a[0][3], b0, b1);
                mma8(acc[1][nb], a[1][0], a[1][1], a[1][2], a[1][3], b0, b1);
            }
        }
    }

#pragma unroll
    for (int mf = 0; mf < 2; mf++) {
        int row = m0 + wm * 32 + mf * 16 + g;
#pragma unroll
        for (int nb = 0; nb < 8; nb++) {
            int col = wn * 64 + nb * 8 + 2 * q;
            *(float2*)&y[(size_t)row * H_ + col] =
                make_float2(__uint_as_float(f2tf(acc[mf][nb][0])), __uint_as_float(f2tf(acc[mf][nb][1])));
            *(float2*)&y[(size_t)(row + 8) * H_ + col] =
                make_float2(__uint_as_float(f2tf(acc[mf][nb][2])), __uint_as_float(f2tf(acc[mf][nb][3])));
        }
    }
}

// ---------------------------------------------------------------------------
// Flash attention, tf32 mma, 2 phase-shifted 4-warp groups per CTA.
// Group gr handles j-tiles jt ≡ gr (mod 2); own Qs/Vs + (m,l,O); merge at end.
// P staged into the group's Qs region (stride 68) between S and O phases.
// ---------------------------------------------------------------------------
#define AGRID 148
#define KQ_S 132
#define V_S  136
#define P_S  68
#define GRP_FLOATS (64 * KQ_S + 64 * V_S)
#define ASMEM_FLOATS (64 * KQ_S + 2 * GRP_FLOATS)
#define ASMEM_BYTES  (ASMEM_FLOATS * 4)

__global__ __launch_bounds__(256) void attn_kernel(float* __restrict__ out) {
    extern __shared__ float sm[];
    float* Ks = sm;
    const int tid  = threadIdx.x;
    const int warp = tid >> 5;
    const int lane = tid & 31;
    const int gr   = warp >> 2;       // group 0/1
    const int w    = warp & 3;        // warp in group
    const int tg   = tid & 127;       // tid in group
    const int g    = lane >> 2;
    const int q    = lane & 3;
    const int rA   = w * 16 + g;      // local rows rA, rA+8
    const int barid = gr + 1;

    float* Qs = Ks + 64 * KQ_S + gr * GRP_FLOATS;
    float* Vs = Qs + 64 * KQ_S;
    float* Qs1 = Ks + 64 * KQ_S + GRP_FLOATS;   // group 1 buffers (for merge)
    float* Vs1 = Qs1 + 64 * KQ_S;
    const unsigned* KsU = (const unsigned*)Ks;
    const unsigned* QsU = (const unsigned*)Qs;
    const unsigned* VsU = (const unsigned*)Vs;
    const unsigned* PsU = (const unsigned*)Qs;  // P reuses Qs with stride P_S

    const int c = blockIdx.x;

    for (int u = 0; u < 2; u++) {
        if (u == 1 && c >= 256 - AGRID) break;
        const int idx    = (u == 0) ? c : 255 - c;
        const int i_tile = 63 - (idx >> 2);
        const int b      = idx & 3;
        const int i0     = i_tile * 64;
        const int nj     = i_tile + 1;

        __syncthreads();  // prior unit fully done with smem
        {
            const float4* ksrc = (const float4*)(g_k + ((size_t)b * T_ + i0) * H_);
#pragma unroll
            for (int t = 0; t < 8; t++) {
                int id = tid + t * 256;
                int row = id >> 5, c4 = id & 31;
                *(float4*)&Ks[row * KQ_S + c4 * 4] = ksrc[id];
            }
        }
        __syncthreads();

        float o[16][4];
#pragma unroll
        for (int hb = 0; hb < 16; hb++)
#pragma unroll
            for (int k = 0; k < 4; k++) o[hb][k] = 0.0f;
        float mrow[2] = {-1e30f, -1e30f};
        float lrow[2] = {0.0f, 0.0f};

        for (int jt = gr; jt < nj; jt += 2) {
            const int j0 = jt * 64;
            barg(barid);  // group done with Vs / P(Qs) from previous iter
            {
                const float4* qsrc = (const float4*)(g_q + ((size_t)b * T_ + j0) * H_);
                const float4* vsrc = (const float4*)(g_v + ((size_t)b * T_ + j0) * H_);
#pragma unroll
                for (int t = 0; t < 16; t++) {
                    int id = tg + t * 128;
                    int row = id >> 5, c4 = id & 31;
                    *(float4*)&Qs[row * KQ_S + c4 * 4] = qsrc[id];
                    *(float4*)&Vs[row * V_S + c4 * 4] = vsrc[id];
                }
            }
            barg(barid);

            // ---- S = K @ Q^T ----
            float s[8][4];
#pragma unroll
            for (int nb = 0; nb < 8; nb++)
#pragma unroll
                for (int k = 0; k < 4; k++) s[nb][k] = 0.0f;
#pragma unroll
            for (int kc = 0; kc < 16; kc++) {
                unsigned a0 = KsU[rA * KQ_S + kc * 8 + q];
                unsigned a1 = KsU[(rA + 8) * KQ_S + kc * 8 + q];
                unsigned a2 = KsU[rA * KQ_S + kc * 8 + q + 4];
                unsigned a3 = KsU[(rA + 8) * KQ_S + kc * 8 + q + 4];
#pragma unroll
                for (int nb = 0; nb < 8; nb++) {
                    unsigned b0 = QsU[(nb * 8 + g) * KQ_S + kc * 8 + q];
                    unsigned b1 = QsU[(nb * 8 + g) * KQ_S + kc * 8 + q + 4];
                    mma8(s[nb], a0, a1, a2, a3, b0, b1);
                }
            }

            // ---- scale + causal mask ----
            const bool diag = (jt == i_tile);
#pragma unroll
            for (int nb = 0; nb < 8; nb++) {
                int jc = j0 + nb * 8 + 2 * q;
                int riA = i0 + rA, riB = riA + 8;
                float v0 = s[nb][0] * 0.03125f, v1 = s[nb][1] * 0.03125f;
                float v2 = s[nb][2] * 0.03125f, v3 = s[nb][3] * 0.03125f;
                if (diag) {
                    if (jc > riA) v0 = -1e30f;
                    if (jc + 1 > riA) v1 = -1e30f;
                    if (jc > riB) v2 = -1e30f;
                    if (jc + 1 > riB) v3 = -1e30f;
                }
                s[nb][0] = v0; s[nb][1] = v1; s[nb][2] = v2; s[nb][3] = v3;
            }

            // ---- online softmax ----
#pragma unroll
            for (int t = 0; t < 2; t++) {
                float tm = -1e30f;
#pragma unroll
                for (int nb = 0; nb < 8; nb++)
                    tm = fmaxf(tm, fmaxf(s[nb][2 * t], s[nb][2 * t + 1]));
                tm = fmaxf(tm, __shfl_xor_sync(0xffffffffu, tm, 1));
                tm = fmaxf(tm, __shfl_xor_sync(0xffffffffu, tm, 2));
                float mn = fmaxf(mrow[t], tm);
                float sc = __expf(mrow[t] - mn);
                mrow[t] = mn;
                float rs = 0.0f;
#pragma unroll
                for (int nb = 0; nb < 8; nb++) {
                    float p0 = __expf(s[nb][2 * t] - mn);
                    float p1 = __expf(s[nb][2 * t + 1] - mn);
                    s[nb][2 * t] = p0; s[nb][2 * t + 1] = p1;
                    rs += p0 + p1;
                }
                rs += __shfl_xor_sync(0xffffffffu, rs, 1);
                rs += __shfl_xor_sync(0xffffffffu, rs, 2);
                lrow[t] = lrow[t] * sc + rs;
#pragma unroll
                for (int hb = 0; hb < 16; hb++) {
                    o[hb][2 * t] *= sc; o[hb][2 * t + 1] *= sc;
                }
            }

            barg(barid);  // all group warps done reading Qs (S-phase B-frags touch all rows)

            // ---- stage P (tf32) into Qs region, stride P_S ----
#pragma unroll
            for (int nb = 0; nb < 8; nb++) {
                *(float2*)&Qs[rA * P_S + nb * 8 + 2 * q] =
                    make_float2(__uint_as_float(f2tf(s[nb][0])), __uint_as_float(f2tf(s[nb][1])));
                *(float2*)&Qs[(rA + 8) * P_S + nb * 8 + 2 * q] =
                    make_float2(__uint_as_float(f2tf(s[nb][2])), __uint_as_float(f2tf(s[nb][3])));
            }
            __syncwarp();

            // ---- O += P @ V ----
#pragma unroll
            for (int t8 = 0; t8 < 8; t8++) {
                unsigned a0 = PsU[rA * P_S + t8 * 8 + q];
                unsigned a1 = PsU[(rA + 8) * P_S + t8 * 8 + q];
                unsigned a2 = PsU[rA * P_S + t8 * 8 + q + 4];
                unsigned a3 = PsU[(rA + 8) * P_S + t8 * 8 + q + 4];
#pragma unroll
                for (int hb = 0; hb < 16; hb++) {
                    unsigned b0 = VsU[(t8 * 8 + q) * V_S + hb * 8 + g];
                    unsigned b1 = VsU[(t8 * 8 + q + 4) * V_S + hb * 8 + g];
                    mma8(o[hb], a0, a1, a2, a3, b0, b1);
                }
            }
        }

        // ---- merge group partials; group 0 writes final ----
        if (gr == 1) {
#pragma unroll
            for (int t = 0; t < 2; t++) {
                if (q == 0) {
                    Vs[rA + t * 8] = mrow[t];
                    Vs[64 + rA + t * 8] = lrow[t];
                }
#pragma unroll
                for (int hb = 0; hb < 16; hb++) {
                    *(float2*)&Qs[(rA + t * 8) * KQ_S + hb * 8 + 2 * q] =
                        make_float2(o[hb][2 * t], o[hb][2 * t + 1]);
                }
            }
        }
        __syncthreads();
        if (gr == 0) {
#pragma unroll
            for (int t = 0; t < 2; t++) {
                int r = rA + t * 8;
                float m1 = Vs1[r], l1 = Vs1[64 + r];
                float mm = fmaxf(mrow[t], m1);
                float f0 = __expf(mrow[t] - mm);
                float f1 = __expf(m1 - mm);
                float inv = 1.0f / (lrow[t] * f0 + l1 * f1);
                size_t rbase = ((size_t)b * T_ + i0 + r) * H_;
#pragma unroll
                for (int hb = 0; hb < 16; hb++) {
                    float2 o1 = *(const float2*)&Qs1[r * KQ_S + hb * 8 + 2 * q];
                    *(float2*)&out[rbase + hb * 8 + 2 * q] =
                        make_float2((o[hb][2 * t] * f0 + o1.x * f1) * inv,
                                    (o[hb][2 * t + 1] * f0 + o1.y * f1) * inv);
                }
            }
        }
    }
}

// ---------------------------------------------------------------------------
extern "C" void kernel_launch(void* const* d_in, const int* in_sizes, int n_in,
                              void* d_out, int out_size) {
    const float* x  = (const float*)d_in[0];
    const float* Wk = (const float*)d_in[1];
    const float* Wq = (const float*)d_in[2];
    const float* Wv = (const float*)d_in[3];
    float* out = (float*)d_out;

    cudaFuncSetAttribute(attn_kernel, cudaFuncAttributeMaxDynamicSharedMemorySize, ASMEM_BYTES);

    proj_kernel<<<dim3(M_ / 128, 3), 256>>>(x, Wk, Wq, Wv);
    attn_kernel<<<AGRID, 256, ASMEM_BYTES>>>(out);
}

// round 4
// speedup vs baseline: 27.4762x; 1.7229x over previous
#include <cuda_runtime.h>
#include <cuda_fp16.h>
#include <math.h>
#include <stdint.h>

#define B_ 4
#define T_ 4096
#define C_ 1024
#define H_ 128
#define M_ (B_ * T_)

// fp16 projection outputs (scratch; no cudaMalloc allowed)
__device__ __half g_k[M_ * H_];
__device__ __half g_q[M_ * H_];
__device__ __half g_v[M_ * H_];

__device__ __forceinline__ uint32_t sptr(const void* p) {
    return (uint32_t)__cvta_generic_to_shared(p);
}
__device__ __forceinline__ uint32_t pkh2(float a, float b) {
    __half2 h = __floats2half2_rn(a, b);
    return *reinterpret_cast<uint32_t*>(&h);
}
__device__ __forceinline__ void ldsm_x4(uint32_t* r, uint32_t a) {
    asm volatile("ldmatrix.sync.aligned.m8n8.x4.shared.b16 {%0,%1,%2,%3}, [%4];"
                 : "=r"(r[0]), "=r"(r[1]), "=r"(r[2]), "=r"(r[3]) : "r"(a));
}
__device__ __forceinline__ void ldsm_x2(uint32_t* r, uint32_t a) {
    asm volatile("ldmatrix.sync.aligned.m8n8.x2.shared.b16 {%0,%1}, [%2];"
                 : "=r"(r[0]), "=r"(r[1]) : "r"(a));
}
__device__ __forceinline__ void ldsm_x2t(uint32_t* r, uint32_t a) {
    asm volatile("ldmatrix.sync.aligned.m8n8.x2.trans.shared.b16 {%0,%1}, [%2];"
                 : "=r"(r[0]), "=r"(r[1]) : "r"(a));
}
__device__ __forceinline__ void mma16(float* c, const uint32_t* a, const uint32_t* b) {
    asm volatile(
        "mma.sync.aligned.m16n8k16.row.col.f32.f16.f16.f32 "
        "{%0,%1,%2,%3},{%4,%5,%6,%7},{%8,%9},{%0,%1,%2,%3};"
        : "+f"(c[0]), "+f"(c[1]), "+f"(c[2]), "+f"(c[3])
        : "r"(a[0]), "r"(a[1]), "r"(a[2]), "r"(a[3]), "r"(b[0]), "r"(b[1]));
}
__device__ __forceinline__ void barg(int id) {
    asm volatile("bar.sync %0, 128;" ::"r"(id) : "memory");
}

// ---------------------------------------------------------------------------
// Fused projections (fp16 mma): y = fp16(x) @ fp16(W), grid (M/128, 3).
// Xs[128][40 halves] (stride 20 words, conflict-free x4), Ws[32][136 halves].
// ---------------------------------------------------------------------------
#define XP_S 40
#define WP_S 136

__global__ __launch_bounds__(256) void proj_kernel(const float* __restrict__ x,
                                                   const float* __restrict__ Wk,
                                                   const float* __restrict__ Wq,
                                                   const float* __restrict__ Wv) {
    __shared__ __half Xs[128 * XP_S];
    __shared__ __half Ws[32 * WP_S];

    const float* W = (blockIdx.y == 0) ? Wk : (blockIdx.y == 1) ? Wq : Wv;
    __half* y = (blockIdx.y == 0) ? g_k : (blockIdx.y == 1) ? g_q : g_v;

    const int tid  = threadIdx.x;
    const int warp = tid >> 5;
    const int lane = tid & 31;
    const int g    = lane >> 2;
    const int q    = lane & 3;
    const int wm   = warp >> 1;
    const int wn   = warp & 1;
    const int m0   = blockIdx.x * 128;

    float acc[2][8][4];
#pragma unroll
    for (int mf = 0; mf < 2; mf++)
#pragma unroll
        for (int nb = 0; nb < 8; nb++)
#pragma unroll
            for (int k = 0; k < 4; k++) acc[mf][nb][k] = 0.0f;

    for (int k0 = 0; k0 < C_; k0 += 32) {
        __syncthreads();
#pragma unroll
        for (int t = 0; t < 4; t++) {
            int idx = tid + t * 256;
            int row = idx >> 3, f4 = idx & 7;
            float4 v = *(const float4*)&x[(size_t)(m0 + row) * C_ + k0 + f4 * 4];
            uint2 u = make_uint2(pkh2(v.x, v.y), pkh2(v.z, v.w));
            *(uint2*)&Xs[row * XP_S + f4 * 4] = u;
        }
#pragma unroll
        for (int t = 0; t < 4; t++) {
            int idx = tid + t * 256;
            int row = idx >> 5, f4 = idx & 31;
            float4 v = *(const float4*)&W[(size_t)(k0 + row) * H_ + f4 * 4];
            uint2 u = make_uint2(pkh2(v.x, v.y), pkh2(v.z, v.w));
            *(uint2*)&Ws[row * WP_S + f4 * 4] = u;
        }
        __syncthreads();

#pragma unroll
        for (int kst = 0; kst < 2; kst++) {
            uint32_t a[2][4];
#pragma unroll
            for (int mf = 0; mf < 2; mf++) {
                int r  = wm * 32 + mf * 16 + (lane & 15);
                int cc = kst * 16 + (lane >> 4) * 8;
                ldsm_x4(a[mf], sptr(&Xs[r * XP_S + cc]));
            }
#pragma unroll
            for (int nb = 0; nb < 8; nb++) {
                uint32_t b[2];
                int vr = kst * 16 + (lane & 7) + 8 * ((lane >> 3) & 1);
                ldsm_x2t(b, sptr(&Ws[vr * WP_S + wn * 64 + nb * 8]));
                mma16(acc[0][nb], a[0], b);
                mma16(acc[1][nb], a[1], b);
            }
        }
    }

#pragma unroll
    for (int mf = 0; mf < 2; mf++) {
        int row = m0 + wm * 32 + mf * 16 + g;
#pragma unroll
        for (int nb = 0; nb < 8; nb++) {
            int col = wn * 64 + nb * 8 + 2 * q;
            *(uint32_t*)&y[(size_t)row * H_ + col] = pkh2(acc[mf][nb][0], acc[mf][nb][1]);
            *(uint32_t*)&y[(size_t)(row + 8) * H_ + col] = pkh2(acc[mf][nb][2], acc[mf][nb][3]);
        }
    }
}

// ---------------------------------------------------------------------------
// Flash attention, fp16 m16n8k16, ldmatrix operands, register-resident P.
// 2 phase-shifted 4-warp groups; K A-fragments cached in regs per unit.
// ---------------------------------------------------------------------------
#define AGRID 148
#define KQ_SH 136                       // halves per row
#define GRP_H (2 * 64 * KQ_SH)          // Q + V per group, in halves
#define ASMEM_HALVES (64 * KQ_SH + 2 * GRP_H)
#define ASMEM_BYTES  (ASMEM_HALVES * 2)
#define MRG_S 132                       // float stride of merge O rows

__global__ __launch_bounds__(256) void attn_kernel(float* __restrict__ out) {
    extern __shared__ __half smh[];
    __half* Ks = smh;
    const int tid  = threadIdx.x;
    const int warp = tid >> 5;
    const int lane = tid & 31;
    const int gr   = warp >> 2;
    const int w    = warp & 3;
    const int tg   = tid & 127;
    const int g    = lane >> 2;
    const int q    = lane & 3;
    const int rA   = w * 16 + g;
    const int barid = gr + 1;

    __half* Qs = Ks + 64 * KQ_SH + gr * GRP_H;
    __half* Vs = Qs + 64 * KQ_SH;
    float* F1 = (float*)(Ks + 64 * KQ_SH + GRP_H);  // merge area = group1 Q+V
    // F1 layout: [0,64) m, [64,128) l, [128 + r*MRG_S + h] O rows

    const int c = blockIdx.x;

    for (int u = 0; u < 2; u++) {
        if (u == 1 && c >= 256 - AGRID) break;
        const int idx    = (u == 0) ? c : 255 - c;
        const int i_tile = 63 - (idx >> 2);
        const int b      = idx & 3;
        const int i0     = i_tile * 64;
        const int nj     = i_tile + 1;

        __syncthreads();  // prior unit fully done with smem
        {
            const uint4* ksrc = (const uint4*)(g_k + ((size_t)b * T_ + i0) * H_);
#pragma unroll
            for (int t = 0; t < 4; t++) {
                int id = tid + t * 256;
                int row = id >> 4, c8 = id & 15;
                *(uint4*)&Ks[row * KQ_SH + c8 * 8] = ksrc[id];
            }
        }
        __syncthreads();

        // Cache K A-fragments for the whole unit (8 k-steps x 4 regs)
        uint32_t ak[8][4];
#pragma unroll
        for (int kst = 0; kst < 8; kst++) {
            int r  = w * 16 + (lane & 15);
            int cc = kst * 16 + (lane >> 4) * 8;
            ldsm_x4(ak[kst], sptr(&Ks[r * KQ_SH + cc]));
        }

        float o[16][4];
#pragma unroll
        for (int hb = 0; hb < 16; hb++)
#pragma unroll
            for (int k = 0; k < 4; k++) o[hb][k] = 0.0f;
        float mrow[2] = {-1e30f, -1e30f};
        float lrow[2] = {0.0f, 0.0f};

        for (int jt = gr; jt < nj; jt += 2) {
            const int j0 = jt * 64;
            barg(barid);  // group done with Qs/Vs from previous iter
            {
                const uint4* qsrc = (const uint4*)(g_q + ((size_t)b * T_ + j0) * H_);
                const uint4* vsrc = (const uint4*)(g_v + ((size_t)b * T_ + j0) * H_);
#pragma unroll
                for (int t = 0; t < 8; t++) {
                    int id = tg + t * 128;
                    int row = id >> 4, c8 = id & 15;
                    *(uint4*)&Qs[row * KQ_SH + c8 * 8] = qsrc[id];
                    *(uint4*)&Vs[row * KQ_SH + c8 * 8] = vsrc[id];
                }
            }
            barg(barid);

            // ---- S = K @ Q^T ----
            float s[8][4];
#pragma unroll
            for (int nb = 0; nb < 8; nb++)
#pragma unroll
                for (int k = 0; k < 4; k++) s[nb][k] = 0.0f;
#pragma unroll
            for (int kst = 0; kst < 8; kst++) {
#pragma unroll
                for (int nb = 0; nb < 8; nb++) {
                    uint32_t bq[2];
                    int qr = nb * 8 + (lane & 7);
                    int cc = kst * 16 + ((lane >> 3) & 1) * 8;
                    ldsm_x2(bq, sptr(&Qs[qr * KQ_SH + cc]));
                    mma16(s[nb], ak[kst], bq);
                }
            }

            // ---- scale + causal mask ----
            const bool diag = (jt == i_tile);
#pragma unroll
            for (int nb = 0; nb < 8; nb++) {
                int jc = j0 + nb * 8 + 2 * q;
                int riA = i0 + rA, riB = riA + 8;
                float v0 = s[nb][0] * 0.03125f, v1 = s[nb][1] * 0.03125f;
                float v2 = s[nb][2] * 0.03125f, v3 = s[nb][3] * 0.03125f;
                if (diag) {
                    if (jc > riA) v0 = -1e30f;
                    if (jc + 1 > riA) v1 = -1e30f;
                    if (jc > riB) v2 = -1e30f;
                    if (jc + 1 > riB) v3 = -1e30f;
                }
                s[nb][0] = v0; s[nb][1] = v1; s[nb][2] = v2; s[nb][3] = v3;
            }

            // ---- online softmax ----
#pragma unroll
            for (int t = 0; t < 2; t++) {
                float tm = -1e30f;
#pragma unroll
                for (int nb = 0; nb < 8; nb++)
                    tm = fmaxf(tm, fmaxf(s[nb][2 * t], s[nb][2 * t + 1]));
                tm = fmaxf(tm, __shfl_xor_sync(0xffffffffu, tm, 1));
                tm = fmaxf(tm, __shfl_xor_sync(0xffffffffu, tm, 2));
                float mn = fmaxf(mrow[t], tm);
                float sc = __expf(mrow[t] - mn);
                mrow[t] = mn;
                float rs = 0.0f;
#pragma unroll
                for (int nb = 0; nb < 8; nb++) {
                    float p0 = __expf(s[nb][2 * t] - mn);
                    float p1 = __expf(s[nb][2 * t + 1] - mn);
                    s[nb][2 * t] = p0; s[nb][2 * t + 1] = p1;
                    rs += p0 + p1;
                }
                rs += __shfl_xor_sync(0xffffffffu, rs, 1);
                rs += __shfl_xor_sync(0xffffffffu, rs, 2);
                lrow[t] = lrow[t] * sc + rs;
#pragma unroll
                for (int hb = 0; hb < 16; hb++) {
                    o[hb][2 * t] *= sc; o[hb][2 * t + 1] *= sc;
                }
            }

            // ---- P fragments straight from registers ----
            uint32_t pa[4][4];
#pragma unroll
            for (int kt = 0; kt < 4; kt++) {
                pa[kt][0] = pkh2(s[2 * kt][0], s[2 * kt][1]);
                pa[kt][1] = pkh2(s[2 * kt][2], s[2 * kt][3]);
                pa[kt][2] = pkh2(s[2 * kt + 1][0], s[2 * kt + 1][1]);
                pa[kt][3] = pkh2(s[2 * kt + 1][2], s[2 * kt + 1][3]);
            }

            // ---- O += P @ V ----
#pragma unroll
            for (int kt = 0; kt < 4; kt++) {
#pragma unroll
                for (int hb = 0; hb < 16; hb++) {
                    uint32_t bv[2];
                    int vr = kt * 16 + (lane & 7) + 8 * ((lane >> 3) & 1);
                    ldsm_x2t(bv, sptr(&Vs[vr * KQ_SH + hb * 8]));
                    mma16(o[hb], pa[kt], bv);
                }
            }
        }

        // ---- merge group partials; group 0 writes final ----
        if (gr == 1) {
#pragma unroll
            for (int t = 0; t < 2; t++) {
                int r = rA + t * 8;
                if (q == 0) { F1[r] = mrow[t]; F1[64 + r] = lrow[t]; }
#pragma unroll
                for (int hb = 0; hb < 16; hb++) {
                    *(float2*)&F1[128 + r * MRG_S + hb * 8 + 2 * q] =
                        make_float2(o[hb][2 * t], o[hb][2 * t + 1]);
                }
            }
        }
        __syncthreads();
        if (gr == 0) {
#pragma unroll
            for (int t = 0; t < 2; t++) {
                int r = rA + t * 8;
                float m1 = F1[r], l1 = F1[64 + r];
                float mm = fmaxf(mrow[t], m1);
                float f0 = __expf(mrow[t] - mm);
                float f1 = __expf(m1 - mm);
                float inv = 1.0f / (lrow[t] * f0 + l1 * f1);
                size_t rbase = ((size_t)b * T_ + i0 + r) * H_;
#pragma unroll
                for (int hb = 0; hb < 16; hb++) {
                    float2 o1 = *(const float2*)&F1[128 + r * MRG_S + hb * 8 + 2 * q];
                    *(float2*)&out[rbase + hb * 8 + 2 * q] =
                        make_float2((o[hb][2 * t] * f0 + o1.x * f1) * inv,
                                    (o[hb][2 * t + 1] * f0 + o1.y * f1) * inv);
                }
            }
        }
    }
}

// ---------------------------------------------------------------------------
extern "C" void kernel_launch(void* const* d_in, const int* in_sizes, int n_in,
                              void* d_out, int out_size) {
    const float* x  = (const float*)d_in[0];
    const float* Wk = (const float*)d_in[1];
    const float* Wq = (const float*)d_in[2];
    const float* Wv = (const float*)d_in[3];
    float* out = (float*)d_out;

    cudaFuncSetAttribute(attn_kernel, cudaFuncAttributeMaxDynamicSharedMemorySize, ASMEM_BYTES);

    proj_kernel<<<dim3(M_ / 128, 3), 256>>>(x, Wk, Wq, Wv);
    attn_kernel<<<AGRID, 256, ASMEM_BYTES>>>(out);
}

// round 7
// speedup vs baseline: 28.3986x; 1.0336x over previous
#include <cuda_runtime.h>
#include <cuda_fp16.h>
#include <math.h>
#include <stdint.h>

#define B_ 4
#define T_ 4096
#define C_ 1024
#define H_ 128
#define M_ (B_ * T_)

// fp16 projection outputs (scratch; no cudaMalloc allowed)
__device__ __half g_k[M_ * H_];
__device__ __half g_q[M_ * H_];
__device__ __half g_v[M_ * H_];

__device__ __forceinline__ uint32_t sptr(const void* p) {
    return (uint32_t)__cvta_generic_to_shared(p);
}
__device__ __forceinline__ uint32_t pkh2(float a, float b) {
    __half2 h = __floats2half2_rn(a, b);
    return *reinterpret_cast<uint32_t*>(&h);
}
__device__ __forceinline__ void ldsm_x4(uint32_t* r, uint32_t a) {
    asm volatile("ldmatrix.sync.aligned.m8n8.x4.shared.b16 {%0,%1,%2,%3}, [%4];"
                 : "=r"(r[0]), "=r"(r[1]), "=r"(r[2]), "=r"(r[3]) : "r"(a));
}
__device__ __forceinline__ void ldsm_x2(uint32_t* r, uint32_t a) {
    asm volatile("ldmatrix.sync.aligned.m8n8.x2.shared.b16 {%0,%1}, [%2];"
                 : "=r"(r[0]), "=r"(r[1]) : "r"(a));
}
__device__ __forceinline__ void ldsm_x2t(uint32_t* r, uint32_t a) {
    asm volatile("ldmatrix.sync.aligned.m8n8.x2.trans.shared.b16 {%0,%1}, [%2];"
                 : "=r"(r[0]), "=r"(r[1]) : "r"(a));
}
__device__ __forceinline__ void mma16(float* c, const uint32_t* a, const uint32_t* b) {
    asm volatile(
        "mma.sync.aligned.m16n8k16.row.col.f32.f16.f16.f32 "
        "{%0,%1,%2,%3},{%4,%5,%6,%7},{%8,%9},{%0,%1,%2,%3};"
        : "+f"(c[0]), "+f"(c[1]), "+f"(c[2]), "+f"(c[3])
        : "r"(a[0]), "r"(a[1]), "r"(a[2]), "r"(a[3]), "r"(b[0]), "r"(b[1]));
}
__device__ __forceinline__ void barg(int id) {
    asm volatile("bar.sync %0, 128;" ::"r"(id) : "memory");
}
__device__ __forceinline__ void cpa16(uint32_t s, const void* g) {
    asm volatile("cp.async.cg.shared.global [%0], [%1], 16;" ::"r"(s), "l"(g));
}
__device__ __forceinline__ void cpcommit() { asm volatile("cp.async.commit_group;"); }
template <int N>
__device__ __forceinline__ void cpwait() {
    asm volatile("cp.async.wait_group %0;" ::"n"(N));
}

// ---------------------------------------------------------------------------
// Fused projections (fp16 mma), cp.async double-buffered fp32 staging.
// grid (M/128, 3). Per iter: prefetch next fp32 tiles; convert current to fp16;
// ldmatrix + m16n8k16 as before.
// ---------------------------------------------------------------------------
#define XP_S 40
#define WP_S 136
// smem carve (bytes): Xf[2][4096]f32, Wf[2][4096]f32, Xs[128*XP_S]h, Ws[32*WP_S]h
#define PJ_XF(b) (b * 16384)
#define PJ_WF(b) (32768 + b * 16384)
#define PJ_XS 65536
#define PJ_WS (65536 + 128 * XP_S * 2)
#define PJ_SMEM (PJ_WS + 32 * WP_S * 2)

__global__ __launch_bounds__(256, 2) void proj_kernel(const float* __restrict__ x,
                                                      const float* __restrict__ Wk,
                                                      const float* __restrict__ Wq,
                                                      const float* __restrict__ Wv) {
    extern __shared__ char psm[];
    float* Xf[2] = {(float*)(psm + PJ_XF(0)), (float*)(psm + PJ_XF(1))};
    float* Wf[2] = {(float*)(psm + PJ_WF(0)), (float*)(psm + PJ_WF(1))};
    __half* Xs = (__half*)(psm + PJ_XS);
    __half* Ws = (__half*)(psm + PJ_WS);

    const float* W = (blockIdx.y == 0) ? Wk : (blockIdx.y == 1) ? Wq : Wv;
    __half* y = (blockIdx.y == 0) ? g_k : (blockIdx.y == 1) ? g_q : g_v;

    const int tid  = threadIdx.x;
    const int warp = tid >> 5;
    const int lane = tid & 31;
    const int g    = lane >> 2;
    const int q    = lane & 3;
    const int wm   = warp >> 1;
    const int wn   = warp & 1;
    const int m0   = blockIdx.x * 128;

    float acc[2][8][4];
#pragma unroll
    for (int mf = 0; mf < 2; mf++)
#pragma unroll
        for (int nb = 0; nb < 8; nb++)
#pragma unroll
            for (int k = 0; k < 4; k++) acc[mf][nb][k] = 0.0f;

    auto pref = [&](int it, int bi) {
        int k0 = it * 32;
#pragma unroll
        for (int t = 0; t < 4; t++) {
            int id = tid + t * 256;
            int row = id >> 3, c4 = id & 7;
            cpa16(sptr(&Xf[bi][id * 4]), &x[(size_t)(m0 + row) * C_ + k0 + c4 * 4]);
        }
#pragma unroll
        for (int t = 0; t < 4; t++) {
            int id = tid + t * 256;
            int row = id >> 5, c4 = id & 31;
            cpa16(sptr(&Wf[bi][id * 4]), &W[(size_t)(k0 + row) * H_ + c4 * 4]);
        }
    };

    pref(0, 0);
    cpcommit();

    for (int it = 0; it < 32; it++) {
        if (it + 1 < 32) pref(it + 1, (it + 1) & 1);
        cpcommit();
        cpwait<1>();
        __syncthreads();

        // convert fp32 staging -> fp16 tiles (conflict-free pairs)
        const int bi = it & 1;
#pragma unroll
        for (int t = 0; t < 8; t++) {
            int p = tid + t * 256;  // pair index [0,2048)
            float2 v = *(const float2*)&Xf[bi][2 * p];
            int row = p >> 4, cp = p & 15;
            *(uint32_t*)&Xs[row * XP_S + 2 * cp] = pkh2(v.x, v.y);
        }
#pragma unroll
        for (int t = 0; t < 8; t++) {
            int p = tid + t * 256;
            float2 v = *(const float2*)&Wf[bi][2 * p];
            int row = p >> 6, cp = p & 63;
            *(uint32_t*)&Ws[row * WP_S + 2 * cp] = pkh2(v.x, v.y);
        }
        __syncthreads();

#pragma unroll
        for (int kst = 0; kst < 2; kst++) {
            uint32_t a[2][4];
#pragma unroll
            for (int mf = 0; mf < 2; mf++) {
                int r  = wm * 32 + mf * 16 + (lane & 15);
                int cc = kst * 16 + (lane >> 4) * 8;
                ldsm_x4(a[mf], sptr(&Xs[r * XP_S + cc]));
            }
#pragma unroll
            for (int nb = 0; nb < 8; nb++) {
                uint32_t bfr[2];
                int vr = kst * 16 + (lane & 7) + 8 * ((lane >> 3) & 1);
                ldsm_x2t(bfr, sptr(&Ws[vr * WP_S + wn * 64 + nb * 8]));
                mma16(acc[0][nb], a[0], bfr);
                mma16(acc[1][nb], a[1], bfr);
            }
        }
    }
    cpwait<0>();

#pragma unroll
    for (int mf = 0; mf < 2; mf++) {
        int row = m0 + wm * 32 + mf * 16 + g;
#pragma unroll
        for (int nb = 0; nb < 8; nb++) {
            int col = wn * 64 + nb * 8 + 2 * q;
            *(uint32_t*)&y[(size_t)row * H_ + col] = pkh2(acc[mf][nb][0], acc[mf][nb][1]);
            *(uint32_t*)&y[(size_t)(row + 8) * H_ + col] = pkh2(acc[mf][nb][2], acc[mf][nb][3]);
        }
    }
}

// ---------------------------------------------------------------------------
// Flash attention, fp16 m16n8k16, cp.async double-buffered Q/V per group.
// 2 phase-shifted 4-warp groups; K A-fragments cached in regs per unit.
// ---------------------------------------------------------------------------
#define AGRID 148
#define KQ_SH 136
#define TILE_H (64 * KQ_SH)              // one 64-row tile, halves
#define ASMEM_HALVES (9 * TILE_H)        // K + 2 groups x 2 bufs x (Q,V)
#define ASMEM_BYTES  (ASMEM_HALVES * 2)
#define MRG_S 132

__global__ __launch_bounds__(256) void attn_kernel(float* __restrict__ out) {
    extern __shared__ __half smh[];
    __half* Ks = smh;
    const int tid  = threadIdx.x;
    const int warp = tid >> 5;
    const int lane = tid & 31;
    const int gr   = warp >> 2;
    const int w    = warp & 3;
    const int tg   = tid & 127;
    const int g    = lane >> 2;
    const int q    = lane & 3;
    const int rA   = w * 16 + g;
    const int barid = gr + 1;

    __half* GB = Ks + TILE_H + gr * 4 * TILE_H;   // group base: [Q0,V0,Q1,V1]
    float* F1 = (float*)(Ks + 7 * TILE_H);        // merge scratch = group1 buf1
    // F1: [0,64) m, [64,128) l, then O rows at 128 + r*MRG_S

    const int c = blockIdx.x;

    for (int u = 0; u < 2; u++) {
        if (u == 1 && c >= 256 - AGRID) break;
        const int idx    = (u == 0) ? c : 255 - c;
        const int i_tile = 63 - (idx >> 2);
        const int b      = idx & 3;
        const int i0     = i_tile * 64;
        const int nj     = i_tile + 1;

        __syncthreads();  // prior unit fully done with smem (incl. merge reads)

        // K tile via cp.async (all 256 threads)
        {
            const uint4* ksrc = (const uint4*)(g_k + ((size_t)b * T_ + i0) * H_);
#pragma unroll
            for (int t = 0; t < 4; t++) {
                int id = tid + t * 256;
                int row = id >> 4, c8 = id & 15;
                cpa16(sptr(&Ks[row * KQ_SH + c8 * 8]), ksrc + id);
            }
        }
        cpcommit();

        auto pref = [&](int jt, int bi) {
            const uint4* qsrc = (const uint4*)(g_q + ((size_t)b * T_ + jt * 64) * H_);
            const uint4* vsrc = (const uint4*)(g_v + ((size_t)b * T_ + jt * 64) * H_);
            __half* Qd = GB + bi * 2 * TILE_H;
            __half* Vd = Qd + TILE_H;
#pragma unroll
            for (int t = 0; t < 8; t++) {
                int id = tg + t * 128;
                int row = id >> 4, c8 = id & 15;
                cpa16(sptr(&Qd[row * KQ_SH + c8 * 8]), qsrc + id);
                cpa16(sptr(&Vd[row * KQ_SH + c8 * 8]), vsrc + id);
            }
        };

        if (gr < nj) pref(gr, 0);
        cpcommit();
        if (gr < nj) cpwait<1>(); else cpwait<0>();
        __syncthreads();  // K landed for everyone

        // Cache K A-fragments for the whole unit
        uint32_t ak[8][4];
#pragma unroll
        for (int kst = 0; kst < 8; kst++) {
            int r  = w * 16 + (lane & 15);
            int cc = kst * 16 + (lane >> 4) * 8;
            ldsm_x4(ak[kst], sptr(&Ks[r * KQ_SH + cc]));
        }

        float o[16][4];
#pragma unroll
        for (int hb = 0; hb < 16; hb++)
#pragma unroll
            for (int k = 0; k < 4; k++) o[hb][k] = 0.0f;
        float mrow[2] = {-1e30f, -1e30f};
        float lrow[2] = {0.0f, 0.0f};

        int pf = 1;
        for (int jt = gr; jt < nj; jt += 2) {
            const int j0 = jt * 64;
            barg(barid);  // group done computing on buf pf (prev iter)
            if (jt + 2 < nj) pref(jt + 2, pf);
            cpcommit();
            cpwait<1>();   // current tile's data complete (this thread)
            barg(barid);   // ... and for the whole group

            const __half* Qs = GB + (pf ^ 1) * 2 * TILE_H;
            const __half* Vs = Qs + TILE_H;
            pf ^= 1;

            // ---- S = K @ Q^T ----
            float s[8][4];
#pragma unroll
            for (int nb = 0; nb < 8; nb++)
#pragma unroll
                for (int k = 0; k < 4; k++) s[nb][k] = 0.0f;
#pragma unroll
            for (int kst = 0; kst < 8; kst++) {
#pragma unroll
                for (int nb = 0; nb < 8; nb++) {
                    uint32_t bq[2];
                    int qr = nb * 8 + (lane & 7);
                    int cc = kst * 16 + ((lane >> 3) & 1) * 8;
                    ldsm_x2(bq, sptr(&Qs[qr * KQ_SH + cc]));
                    mma16(s[nb], ak[kst], bq);
                }
            }

            // ---- scale + causal mask ----
            const bool diag = (jt == i_tile);
#pragma unroll
            for (int nb = 0; nb < 8; nb++) {
                int jc = j0 + nb * 8 + 2 * q;
                int riA = i0 + rA, riB = riA + 8;
                float v0 = s[nb][0] * 0.03125f, v1 = s[nb][1] * 0.03125f;
                float v2 = s[nb][2] * 0.03125f, v3 = s[nb][3] * 0.03125f;
                if (diag) {
                    if (jc > riA) v0 = -1e30f;
                    if (jc + 1 > riA) v1 = -1e30f;
                    if (jc > riB) v2 = -1e30f;
                    if (jc + 1 > riB) v3 = -1e30f;
                }
                s[nb][0] = v0; s[nb][1] = v1; s[nb][2] = v2; s[nb][3] = v3;
            }

            // ---- online softmax ----
#pragma unroll
            for (int t = 0; t < 2; t++) {
                float tm = -1e30f;
#pragma unroll
                for (int nb = 0; nb < 8; nb++)
                    tm = fmaxf(tm, fmaxf(s[nb][2 * t], s[nb][2 * t + 1]));
                tm = fmaxf(tm, __shfl_xor_sync(0xffffffffu, tm, 1));
                tm = fmaxf(tm, __shfl_xor_sync(0xffffffffu, tm, 2));
                float mn = fmaxf(mrow[t], tm);
                float sc = __expf(mrow[t] - mn);
                mrow[t] = mn;
                float rs = 0.0f;
#pragma unroll
                for (int nb = 0; nb < 8; nb++) {
                    float p0 = __expf(s[nb][2 * t] - mn);
                    float p1 = __expf(s[nb][2 * t + 1] - mn);
                    s[nb][2 * t] = p0; s[nb][2 * t + 1] = p1;
                    rs += p0 + p1;
                }
                rs += __shfl_xor_sync(0xffffffffu, rs, 1);
                rs += __shfl_xor_sync(0xffffffffu, rs, 2);
                lrow[t] = lrow[t] * sc + rs;
#pragma unroll
                for (int hb = 0; hb < 16; hb++) {
                    o[hb][2 * t] *= sc; o[hb][2 * t + 1] *= sc;
                }
            }

            // ---- P fragments straight from registers ----
            uint32_t pa[4][4];
#pragma unroll
            for (int kt = 0; kt < 4; kt++) {
                pa[kt][0] = pkh2(s[2 * kt][0], s[2 * kt][1]);
                pa[kt][1] = pkh2(s[2 * kt][2], s[2 * kt][3]);
                pa[kt][2] = pkh2(s[2 * kt + 1][0], s[2 * kt + 1][1]);
                pa[kt][3] = pkh2(s[2 * kt + 1][2], s[2 * kt + 1][3]);
            }

            // ---- O += P @ V ----
#pragma unroll
            for (int kt = 0; kt < 4; kt++) {
#pragma unroll
                for (int hb = 0; hb < 16; hb++) {
                    uint32_t bv[2];
                    int vr = kt * 16 + (lane & 7) + 8 * ((lane >> 3) & 1);
                    ldsm_x2t(bv, sptr(&Vs[vr * KQ_SH + hb * 8]));
                    mma16(o[hb], pa[kt], bv);
                }
            }
        }
        cpwait<0>();
        barg(barid);  // group fully done with its buffers before merge reuse

        // ---- merge group partials; group 0 writes final ----
        if (gr == 1) {
#pragma unroll
            for (int t = 0; t < 2; t++) {
                int r = rA + t * 8;
                if (q == 0) { F1[r] = mrow[t]; F1[64 + r] = lrow[t]; }
#pragma unroll
                for (int hb = 0; hb < 16; hb++) {
                    *(float2*)&F1[128 + r * MRG_S + hb * 8 + 2 * q] =
                        make_float2(o[hb][2 * t], o[hb][2 * t + 1]);
                }
            }
        }
        __syncthreads();
        if (gr == 0) {
#pragma unroll
            for (int t = 0; t < 2; t++) {
                int r = rA + t * 8;
                float m1 = F1[r], l1 = F1[64 + r];
                float mm = fmaxf(mrow[t], m1);
                float f0 = __expf(mrow[t] - mm);
                float f1 = __expf(m1 - mm);
                float inv = 1.0f / (lrow[t] * f0 + l1 * f1);
                size_t rbase = ((size_t)b * T_ + i0 + r) * H_;
#pragma unroll
                for (int hb = 0; hb < 16; hb++) {
                    float2 o1 = *(const float2*)&F1[128 + r * MRG_S + hb * 8 + 2 * q];
                    *(float2*)&out[rbase + hb * 8 + 2 * q] =
                        make_float2((o[hb][2 * t] * f0 + o1.x * f1) * inv,
                                    (o[hb][2 * t + 1] * f0 + o1.y * f1) * inv);
                }
            }
        }
    }
}

// ---------------------------------------------------------------------------
extern "C" void kernel_launch(void* const* d_in, const int* in_sizes, int n_in,
                              void* d_out, int out_size) {
    const float* x  = (const float*)d_in[0];
    const float* Wk = (const float*)d_in[1];
    const float* Wq = (const float*)d_in[2];
    const float* Wv = (const float*)d_in[3];
    float* out = (float*)d_out;

    cudaFuncSetAttribute(proj_kernel, cudaFuncAttributeMaxDynamicSharedMemorySize, PJ_SMEM);
    cudaFuncSetAttribute(attn_kernel, cudaFuncAttributeMaxDynamicSharedMemorySize, ASMEM_BYTES);

    proj_kernel<<<dim3(M_ / 128, 3), 256, PJ_SMEM>>>(x, Wk, Wq, Wv);
    attn_kernel<<<AGRID, 256, ASMEM_BYTES>>>(out);
}

// round 10
// speedup vs baseline: 33.3496x; 1.1743x over previous
#include <cuda_runtime.h>
#include <cuda_fp16.h>
#include <math.h>
#include <stdint.h>

#define B_ 4
#define T_ 4096
#define C_ 1024
#define H_ 128
#define M_ (B_ * T_)

// fp16 scratch (no cudaMalloc allowed)
__device__ __half g_k[M_ * H_];
__device__ __half g_q[M_ * H_];
__device__ __half g_v[M_ * H_];
__device__ __half g_wh[3 * C_ * H_];

// log2(e) / 32  (softmax done in exp2 domain)
#define SM_SCALE 0.04508422f

__device__ __forceinline__ uint32_t sptr(const void* p) {
    return (uint32_t)__cvta_generic_to_shared(p);
}
__device__ __forceinline__ uint32_t pkh2(float a, float b) {
    __half2 h = __floats2half2_rn(a, b);
    return *reinterpret_cast<uint32_t*>(&h);
}
__device__ __forceinline__ float ex2(float x) {
    float y;
    asm("ex2.approx.f32 %0, %1;" : "=f"(y) : "f"(x));
    return y;
}
__device__ __forceinline__ void ldsm_x4(uint32_t* r, uint32_t a) {
    asm volatile("ldmatrix.sync.aligned.m8n8.x4.shared.b16 {%0,%1,%2,%3}, [%4];"
                 : "=r"(r[0]), "=r"(r[1]), "=r"(r[2]), "=r"(r[3]) : "r"(a));
}
__device__ __forceinline__ void ldsm_x2(uint32_t* r, uint32_t a) {
    asm volatile("ldmatrix.sync.aligned.m8n8.x2.shared.b16 {%0,%1}, [%2];"
                 : "=r"(r[0]), "=r"(r[1]) : "r"(a));
}
__device__ __forceinline__ void ldsm_x2t(uint32_t* r, uint32_t a) {
    asm volatile("ldmatrix.sync.aligned.m8n8.x2.trans.shared.b16 {%0,%1}, [%2];"
                 : "=r"(r[0]), "=r"(r[1]) : "r"(a));
}
__device__ __forceinline__ void mma16(float* c, const uint32_t* a, const uint32_t* b) {
    asm volatile(
        "mma.sync.aligned.m16n8k16.row.col.f32.f16.f16.f32 "
        "{%0,%1,%2,%3},{%4,%5,%6,%7},{%8,%9},{%0,%1,%2,%3};"
        : "+f"(c[0]), "+f"(c[1]), "+f"(c[2]), "+f"(c[3])
        : "r"(a[0]), "r"(a[1]), "r"(a[2]), "r"(a[3]), "r"(b[0]), "r"(b[1]));
}
__device__ __forceinline__ void barg(int id) {
    asm volatile("bar.sync %0, 128;" ::"r"(id) : "memory");
}
__device__ __forceinline__ void cpa16(uint32_t s, const void* g) {
    asm volatile("cp.async.cg.shared.global [%0], [%1], 16;" ::"r"(s), "l"(g));
}
__device__ __forceinline__ void cpcommit() { asm volatile("cp.async.commit_group;"); }
template <int N>
__device__ __forceinline__ void cpwait() {
    asm volatile("cp.async.wait_group %0;" ::"n"(N));
}

// ---------------------------------------------------------------------------
// W converter: Wk|Wq|Wv fp32 -> g_wh fp16 (3 * 1024 * 128)
// ---------------------------------------------------------------------------
__global__ __launch_bounds__(256) void wconv_kernel(const float* __restrict__ Wk,
                                                    const float* __restrict__ Wq,
                                                    const float* __restrict__ Wv) {
    int idx = blockIdx.x * 256 + threadIdx.x;  // float4 index, 98304 total
    for (; idx < 3 * C_ * H_ / 4; idx += gridDim.x * 256) {
        int mat = idx >> 15;
        int rem = idx & 32767;
        const float* src = (mat == 0) ? Wk : (mat == 1) ? Wq : Wv;
        float4 v = *(const float4*)&src[rem * 4];
        uint2 u = make_uint2(pkh2(v.x, v.y), pkh2(v.z, v.w));
        *(uint2*)&g_wh[(size_t)mat * C_ * H_ + rem * 4] = u;
    }
}

// ---------------------------------------------------------------------------
// Triple projection: one CTA computes k,q,v for a 64-row slab of x.
// grid 256, 256 threads. x loaded+converted once; W fp16 streamed from g_wh.
// ---------------------------------------------------------------------------
#define XP_S 40
#define WP_S 136
#define PJ_XF(b) ((b) * 8192)            // 64x32 f32 = 8 KB per buf
#define PJ_XS 16384                      // 64*XP_S halves = 5120 B
#define PJ_WS(b) (21504 + (b) * 26112)   // 3*32*WP_S halves = 26112 B per buf
#define PJ_SMEM (21504 + 2 * 26112)

__global__ __launch_bounds__(256) void proj_kernel(const float* __restrict__ x) {
    extern __shared__ char psm[];
    __half* Xs = (__half*)(psm + PJ_XS);

    const int tid  = threadIdx.x;
    const int warp = tid >> 5;
    const int lane = tid & 31;
    const int g    = lane >> 2;
    const int q    = lane & 3;
    const int wm   = warp >> 1;  // 0..3 -> 16-row strip
    const int wn   = warp & 1;   // 0..1 -> 64-col half
    const int m0   = blockIdx.x * 64;

    float acc[3][8][4];
#pragma unroll
    for (int mt = 0; mt < 3; mt++)
#pragma unroll
        for (int nb = 0; nb < 8; nb++)
#pragma unroll
            for (int k = 0; k < 4; k++) acc[mt][nb][k] = 0.0f;

    auto pref = [&](int it, int bi) {
        int k0 = it * 32;
        // x slab: 512 16B chunks
#pragma unroll
        for (int t = 0; t < 2; t++) {
            int id = tid + t * 256;
            int row = id >> 3, c4 = id & 7;
            cpa16(sptr(psm + PJ_XF(bi) + id * 16), &x[(size_t)(m0 + row) * C_ + k0 + c4 * 4]);
        }
        // W chunk (3 mats x 32 x 128 halves): 1536 16B chunks
#pragma unroll
        for (int t = 0; t < 6; t++) {
            int id = tid + t * 256;
            int mat = id >> 9, rem = id & 511;
            int row = rem >> 4, c8 = rem & 15;
            cpa16(sptr(psm + PJ_WS(bi) + ((mat * 32 + row) * WP_S + c8 * 8) * 2),
                  &g_wh[(size_t)mat * C_ * H_ + (size_t)(k0 + row) * H_ + c8 * 8]);
        }
    };

    pref(0, 0);
    cpcommit();

    for (int it = 0; it < 32; it++) {
        const int bi = it & 1;
        if (it + 1 < 32) pref(it + 1, bi ^ 1);
        cpcommit();
        cpwait<1>();
        __syncthreads();

        // convert x staging fp32 -> fp16 tile
        const float* Xf = (const float*)(psm + PJ_XF(bi));
#pragma unroll
        for (int t = 0; t < 4; t++) {
            int p = tid + t * 256;  // pair index [0,1024)
            float2 v = *(const float2*)&Xf[2 * p];
            int row = p >> 4, cp = p & 15;
            *(uint32_t*)&Xs[row * XP_S + 2 * cp] = pkh2(v.x, v.y);
        }
        __syncthreads();

        const __half* Ws = (const __half*)(psm + PJ_WS(bi));
#pragma unroll
        for (int kst = 0; kst < 2; kst++) {
            uint32_t a[4];
            int r  = wm * 16 + (lane & 15);
            int cc = kst * 16 + (lane >> 4) * 8;
            ldsm_x4(a, sptr(&Xs[r * XP_S + cc]));
            int vr = kst * 16 + (lane & 7) + 8 * ((lane >> 3) & 1);
#pragma unroll
            for (int mt = 0; mt < 3; mt++) {
#pragma unroll
                for (int nb = 0; nb < 8; nb++) {
                    uint32_t bfr[2];
                    ldsm_x2t(bfr, sptr(&Ws[(mt * 32 + vr) * WP_S + wn * 64 + nb * 8]));
                    mma16(acc[mt][nb], a, bfr);
                }
            }
        }
        __syncthreads();  // all warps done reading Ws[bi] before it is re-prefetched
    }
    cpwait<0>();

#pragma unroll
    for (int mt = 0; mt < 3; mt++) {
        __half* y = (mt == 0) ? g_k : (mt == 1) ? g_q : g_v;
        int row = m0 + wm * 16 + g;
#pragma unroll
        for (int nb = 0; nb < 8; nb++) {
            int col = wn * 64 + nb * 8 + 2 * q;
            *(uint32_t*)&y[(size_t)row * H_ + col] = pkh2(acc[mt][nb][0], acc[mt][nb][1]);
            *(uint32_t*)&y[(size_t)(row + 8) * H_ + col] = pkh2(acc[mt][nb][2], acc[mt][nb][3]);
        }
    }
}

// ---------------------------------------------------------------------------
// Flash attention: fp16 m16n8k16, 3 phase-shifted 4-warp groups (384 thr),
// cp.async double-buffered Q/V per group, exp2-domain softmax, 3-way merge.
// ---------------------------------------------------------------------------
#define AGRID 148
#define KQ_SH 136
#define TILE_H (64 * KQ_SH)
#define ASMEM_HALVES (13 * TILE_H)       // K + 3 groups x 2 bufs x (Q,V)
#define ASMEM_BYTES  (ASMEM_HALVES * 2)  // 226304 B
#define MRG_S 132

__global__ __launch_bounds__(384) void attn_kernel(float* __restrict__ out) {
    extern __shared__ __half smh[];
    __half* Ks = smh;
    const int tid  = threadIdx.x;
    const int warp = tid >> 5;
    const int lane = tid & 31;
    const int gr   = warp >> 2;       // group 0..2
    const int w    = warp & 3;
    const int tg   = tid & 127;
    const int g    = lane >> 2;
    const int q    = lane & 3;
    const int rA   = w * 16 + g;
    const int barid = gr + 1;

    __half* GB = Ks + TILE_H + gr * 4 * TILE_H;  // [Q0,V0,Q1,V1]
    float* F1 = (float*)(Ks + TILE_H * 5);       // group1 buffers (merge scratch)
    float* F2 = (float*)(Ks + TILE_H * 9);       // group2 buffers
    // F layout: [0,64) m, [64,128) l, then O rows at 128 + r*MRG_S

    const int c = blockIdx.x;

    for (int u = 0; u < 2; u++) {
        if (u == 1 && c >= 256 - AGRID) break;
        const int idx    = (u == 0) ? c : 255 - c;
        const int i_tile = 63 - (idx >> 2);
        const int b      = idx & 3;
        const int i0     = i_tile * 64;
        const int nj     = i_tile + 1;

        __syncthreads();  // prior unit fully done with smem

        // K tile via cp.async (all 384 threads, 1024 chunks)
        {
            const uint4* ksrc = (const uint4*)(g_k + ((size_t)b * T_ + i0) * H_);
#pragma unroll
            for (int t = 0; t < 3; t++) {
                int id = tid + t * 384;
                if (id < 1024) {
                    int row = id >> 4, c8 = id & 15;
                    cpa16(sptr(&Ks[row * KQ_SH + c8 * 8]), ksrc + id);
                }
            }
        }
        cpcommit();

        auto pref = [&](int jt, int bi) {
            const uint4* qsrc = (const uint4*)(g_q + ((size_t)b * T_ + jt * 64) * H_);
            const uint4* vsrc = (const uint4*)(g_v + ((size_t)b * T_ + jt * 64) * H_);
            __half* Qd = GB + bi * 2 * TILE_H;
            __half* Vd = Qd + TILE_H;
#pragma unroll
            for (int t = 0; t < 8; t++) {
                int id = tg + t * 128;
                int row = id >> 4, c8 = id & 15;
                cpa16(sptr(&Qd[row * KQ_SH + c8 * 8]), qsrc + id);
                cpa16(sptr(&Vd[row * KQ_SH + c8 * 8]), vsrc + id);
            }
        };

        if (gr < nj) pref(gr, 0);
        cpcommit();
        if (gr < nj) cpwait<1>(); else cpwait<0>();
        __syncthreads();  // K landed for everyone

        float o[16][4];
#pragma unroll
        for (int hb = 0; hb < 16; hb++)
#pragma unroll
            for (int k = 0; k < 4; k++) o[hb][k] = 0.0f;
        float mrow[2] = {-1e30f, -1e30f};
        float lrow[2] = {0.0f, 0.0f};

        int pf = 1;
        for (int jt = gr; jt < nj; jt += 3) {
            const int j0 = jt * 64;
            barg(barid);  // group done computing on buf pf (2 iters ago)
            if (jt + 3 < nj) pref(jt + 3, pf);
            cpcommit();
            cpwait<1>();
            barg(barid);  // whole group sees current tile

            const __half* Qs = GB + (pf ^ 1) * 2 * TILE_H;
            const __half* Vs = Qs + TILE_H;
            pf ^= 1;

            // ---- S = K @ Q^T ----
            float s[8][4];
#pragma unroll
            for (int nb = 0; nb < 8; nb++)
#pragma unroll
                for (int k = 0; k < 4; k++) s[nb][k] = 0.0f;
#pragma unroll
            for (int kst = 0; kst < 8; kst++) {
                uint32_t a[4];
                int cc = kst * 16 + (lane >> 4) * 8;
                ldsm_x4(a, sptr(&Ks[(w * 16 + (lane & 15)) * KQ_SH + cc]));
                int qcc = kst * 16 + ((lane >> 3) & 1) * 8;
#pragma unroll
                for (int nb = 0; nb < 8; nb++) {
                    uint32_t bq[2];
                    ldsm_x2(bq, sptr(&Qs[(nb * 8 + (lane & 7)) * KQ_SH + qcc]));
                    mma16(s[nb], a, bq);
                }
            }

            // ---- scale (exp2 domain) + causal mask ----
            const bool diag = (jt == i_tile);
#pragma unroll
            for (int nb = 0; nb < 8; nb++) {
                int jc = j0 + nb * 8 + 2 * q;
                int riA = i0 + rA, riB = riA + 8;
                float v0 = s[nb][0] * SM_SCALE, v1 = s[nb][1] * SM_SCALE;
                float v2 = s[nb][2] * SM_SCALE, v3 = s[nb][3] * SM_SCALE;
                if (diag) {
                    if (jc > riA) v0 = -1e30f;
                    if (jc + 1 > riA) v1 = -1e30f;
                    if (jc > riB) v2 = -1e30f;
                    if (jc + 1 > riB) v3 = -1e30f;
                }
                s[nb][0] = v0; s[nb][1] = v1; s[nb][2] = v2; s[nb][3] = v3;
            }

            // ---- online softmax (exp2) ----
#pragma unroll
            for (int t = 0; t < 2; t++) {
                float tm = -1e30f;
#pragma unroll
                for (int nb = 0; nb < 8; nb++)
                    tm = fmaxf(tm, fmaxf(s[nb][2 * t], s[nb][2 * t + 1]));
                tm = fmaxf(tm, __shfl_xor_sync(0xffffffffu, tm, 1));
                tm = fmaxf(tm, __shfl_xor_sync(0xffffffffu, tm, 2));
                float mn = fmaxf(mrow[t], tm);
                float sc = ex2(mrow[t] - mn);
                mrow[t] = mn;
                float rs = 0.0f;
#pragma unroll
                for (int nb = 0; nb < 8; nb++) {
                    float p0 = ex2(s[nb][2 * t] - mn);
                    float p1 = ex2(s[nb][2 * t + 1] - mn);
                    s[nb][2 * t] = p0; s[nb][2 * t + 1] = p1;
                    rs += p0 + p1;
                }
                rs += __shfl_xor_sync(0xffffffffu, rs, 1);
                rs += __shfl_xor_sync(0xffffffffu, rs, 2);
                lrow[t] = lrow[t] * sc + rs;
#pragma unroll
                for (int hb = 0; hb < 16; hb++) {
                    o[hb][2 * t] *= sc; o[hb][2 * t + 1] *= sc;
                }
            }

            // ---- P fragments from registers ----
            uint32_t pa[4][4];
#pragma unroll
            for (int kt = 0; kt < 4; kt++) {
                pa[kt][0] = pkh2(s[2 * kt][0], s[2 * kt][1]);
                pa[kt][1] = pkh2(s[2 * kt][2], s[2 * kt][3]);
                pa[kt][2] = pkh2(s[2 * kt + 1][0], s[2 * kt + 1][1]);
                pa[kt][3] = pkh2(s[2 * kt + 1][2], s[2 * kt + 1][3]);
            }

            // ---- O += P @ V ----
#pragma unroll
            for (int kt = 0; kt < 4; kt++) {
                int vr = kt * 16 + (lane & 7) + 8 * ((lane >> 3) & 1);
#pragma unroll
                for (int hb = 0; hb < 16; hb++) {
                    uint32_t bv[2];
                    ldsm_x2t(bv, sptr(&Vs[vr * KQ_SH + hb * 8]));
                    mma16(o[hb], pa[kt], bv);
                }
            }
        }
        cpwait<0>();
        barg(barid);  // group fully done with its buffers

        // ---- 3-way merge; group 0 writes final ----
        if (gr >= 1) {
            float* F = (gr == 1) ? F1 : F2;
#pragma unroll
            for (int t = 0; t < 2; t++) {
                int r = rA + t * 8;
                if (q == 0) { F[r] = mrow[t]; F[64 + r] = lrow[t]; }
#pragma unroll
                for (int hb = 0; hb < 16; hb++) {
                    *(float2*)&F[128 + r * MRG_S + hb * 8 + 2 * q] =
                        make_float2(o[hb][2 * t], o[hb][2 * t + 1]);
                }
            }
        }
        __syncthreads();
        if (gr == 0) {
#pragma unroll
            for (int t = 0; t < 2; t++) {
                int r = rA + t * 8;
                float m1 = F1[r], l1 = F1[64 + r];
                float m2 = F2[r], l2 = F2[64 + r];
                float mm = fmaxf(mrow[t], fmaxf(m1, m2));
                float f0 = ex2(mrow[t] - mm);
                float f1 = ex2(m1 - mm);
                float f2 = ex2(m2 - mm);
                float inv = 1.0f / (lrow[t] * f0 + l1 * f1 + l2 * f2);
                size_t rbase = ((size_t)b * T_ + i0 + r) * H_;
#pragma unroll
                for (int hb = 0; hb < 16; hb++) {
                    float2 o1 = *(const float2*)&F1[128 + r * MRG_S + hb * 8 + 2 * q];
                    float2 o2 = *(const float2*)&F2[128 + r * MRG_S + hb * 8 + 2 * q];
                    *(float2*)&out[rbase + hb * 8 + 2 * q] =
                        make_float2((o[hb][2 * t] * f0 + o1.x * f1 + o2.x * f2) * inv,
                                    (o[hb][2 * t + 1] * f0 + o1.y * f1 + o2.y * f2) * inv);
                }
            }
        }
    }
}

// ---------------------------------------------------------------------------
extern "C" void kernel_launch(void* const* d_in, const int* in_sizes, int n_in,
                              void* d_out, int out_size) {
    const float* x  = (const float*)d_in[0];
    const float* Wk = (const float*)d_in[1];
    const float* Wq = (const float*)d_in[2];
    const float* Wv = (const float*)d_in[3];
    float* out = (float*)d_out;

    cudaFuncSetAttribute(proj_kernel, cudaFuncAttributeMaxDynamicSharedMemorySize, PJ_SMEM);
    cudaFuncSetAttribute(attn_kernel, cudaFuncAttributeMaxDynamicSharedMemorySize, ASMEM_BYTES);

    wconv_kernel<<<128, 256>>>(Wk, Wq, Wv);
    proj_kernel<<<M_ / 64, 256, PJ_SMEM>>>(x);
    attn_kernel<<<AGRID, 384, ASMEM_BYTES>>>(out);
}